// round 8
// baseline (speedup 1.0000x reference)
#include <cuda_runtime.h>

#define FULL 0xFFFFFFFFu

__device__ __forceinline__ unsigned long long pack2(float a, float b) {
    unsigned long long r;
    asm("mov.b64 %0, {%1, %2};" : "=l"(r) : "f"(a), "f"(b));
    return r;
}
__device__ __forceinline__ void unpack2(unsigned long long p, float& a, float& b) {
    asm("mov.b64 {%0, %1}, %2;" : "=f"(a), "=f"(b) : "l"(p));
}
__device__ __forceinline__ unsigned long long fma2(unsigned long long a,
                                                   unsigned long long b,
                                                   unsigned long long c) {
    unsigned long long d;
    asm("fma.rn.f32x2 %0, %1, %2, %3;" : "=l"(d) : "l"(a), "l"(b), "l"(c));
    return d;
}
__device__ __forceinline__ unsigned long long add2(unsigned long long a,
                                                   unsigned long long b) {
    unsigned long long d;
    asm("add.rn.f32x2 %0, %1, %2;" : "=l"(d) : "l"(a), "l"(b));
    return d;
}

__device__ __forceinline__ float fast_sigmoid(float x) {
    return __fdividef(1.0f, 1.0f + __expf(-x));
}

// One CTA per TWO batches, 160 threads, grid 128 (one CTA/SM, single wave).
// HALF-STEP PIPELINE (round 8): the two independent batch recurrences are
// phase-shifted by half a step. Even slot: dot0(t) burst overlaps tail1(t-1)
// whose z inputs were computed BEFORE the preceding barrier (pure register
// carry, no dependency on this slot); odd slot: dot1(t) overlaps tail0(t).
// Every slot's ~130-cycle nonlinear tail hides under the other batch's fma
// burst. h0/h1 single-buffered (each STS->LDS pair is barrier-separated).
// Threads 0..127: layer-0; thread = (unit u, type); type0 owns (i,j),
// type1 owns (f,o); weights register-resident f32x2, shared by both batches.
// Threads 128..159 (warp 4): layer-1 (units=1) + dense; batch0 in even
// slots, batch1 in odd slots, full-warp dot (8 fma + 3 shfl reduce).
__global__ __launch_bounds__(160, 1)
void lstm_stack_kernel(const float* __restrict__ x,
                       const float* __restrict__ W0,
                       const float* __restrict__ b0,
                       const float* __restrict__ W1,
                       const float* __restrict__ b1,
                       const float* __restrict__ Wd,
                       const float* __restrict__ bd,
                       float* __restrict__ out)
{
    constexpr int T = 2048;

    const int bb   = blockIdx.x;      // batch pair
    const int tid  = threadIdx.x;
    const int lane = tid & 31;
    const int wid  = tid >> 5;

    __shared__ __align__(16) float x_sh[2][T];
    __shared__ __align__(16) float h0_sh[64];
    __shared__ __align__(16) float h1_sh[64];
    __shared__ float red[5];
    __shared__ float inv_sh[2];

    // ---- Phase 0: load both x tiles, l2-normalize over time ----
    for (int bi = 0; bi < 2; ++bi) {
        const float* xb = x + (2 * bb + bi) * T;
        float ps = 0.f;
        for (int i = tid; i < T; i += 160) {
            float v = xb[i];
            x_sh[bi][i] = v;
            ps = fmaf(v, v, ps);
        }
        #pragma unroll
        for (int o = 16; o > 0; o >>= 1) ps += __shfl_xor_sync(FULL, ps, o);
        if (lane == 0) red[wid] = ps;
        __syncthreads();
        if (tid == 0) {
            float s = 0.f;
            #pragma unroll
            for (int i = 0; i < 5; ++i) s += red[i];
            inv_sh[bi] = rsqrtf(fmaxf(s, 1e-12f));
        }
        __syncthreads();               // also protects red[] reuse
    }
    {
        float i0 = inv_sh[0], i1 = inv_sh[1];
        for (int i = tid; i < T; i += 160) {
            x_sh[0][i] *= i0;
            x_sh[1][i] *= i1;
        }
    }
    if (tid < 64) { h0_sh[tid] = 0.f; h1_sh[tid] = 0.f; }   // h_{-1} = 0
    // (ordered by the first barrier inside the main loop)

    // ---- Per-thread persistent state / weights ----
    const int u    = tid >> 1;
    const int type = tid & 1;           // 0: (i,j)   1: (f,o)
    unsigned long long wpa[32], wpb[32];
    float wxa = 0.f, wxb = 0.f, ba = 0.f, bb2 = 0.f;
    float c0_0 = 0.f, c0_1 = 0.f;
    float za0 = 0.f, zb0 = 0.f, za1 = 0.f, zb1 = 0.f;   // carried across slots

    // layer-1 (warp 4): full-warp layout, batch selected by slot parity
    const int l1g  = lane & 3;          // gate
    const int l1bk = lane >> 2;         // bank 0..7
    float w1r[8];
    float w1h = 0.f, b1v = 0.f, wdv = 0.f, bdv = 0.f;
    float c1_0 = 0.f, h1L_0 = 0.f, c1_1 = 0.f, h1L_1 = 0.f;

    if (tid < 128) {
        const int ca = u + (type ? 128 : 0);   // i or f column
        const int cb = ca + 64;                // j or o column
        wxa = W0[ca];
        wxb = W0[cb];
        ba  = b0[ca] + (type ? 1.0f : 0.0f);   // fold FORGET_BIAS
        bb2 = b0[cb];
        #pragma unroll
        for (int p = 0; p < 32; ++p) {
            wpa[p] = pack2(W0[(1 + 2 * p) * 256 + ca], W0[(2 + 2 * p) * 256 + ca]);
            wpb[p] = pack2(W0[(1 + 2 * p) * 256 + cb], W0[(2 + 2 * p) * 256 + cb]);
        }
    } else {
        #pragma unroll
        for (int j = 0; j < 8; ++j)
            w1r[j] = W1[(l1bk + 8 * j) * 4 + l1g];
        w1h = W1[64 * 4 + l1g];
        b1v = b1[l1g];
        wdv = Wd[0];
        bdv = bd[0];
    }

    // ---- Main pipelined recurrence ----
    #pragma unroll 1
    for (int t = 0; t <= T; ++t) {
        const int tt  = (t < T) ? t : 0;
        const float xt0 = x_sh[0][tt];
        const float xt1 = x_sh[1][tt];

        // ================= EVEN slot =================
        // dot0(t) ; tail1(t-1) ; layer1 batch0 step t-1
        if (tid < 128) {
            if (t < T) {
                const ulonglong2* hp = (const ulonglong2*)h0_sh;
                unsigned long long a0 = pack2(fmaf(xt0, wxa, ba), 0.f);
                unsigned long long a1 = pack2(0.f, 0.f);
                unsigned long long e0 = pack2(fmaf(xt0, wxb, bb2), 0.f);
                unsigned long long e1 = pack2(0.f, 0.f);
                #pragma unroll
                for (int i = 0; i < 16; ++i) {
                    ulonglong2 hv = hp[i];
                    a0 = fma2(hv.x, wpa[2 * i],     a0);
                    a1 = fma2(hv.y, wpa[2 * i + 1], a1);
                    e0 = fma2(hv.x, wpb[2 * i],     e0);
                    e1 = fma2(hv.y, wpb[2 * i + 1], e1);
                }
                float lo, hi;
                unpack2(add2(a0, a1), lo, hi); za0 = lo + hi;
                unpack2(add2(e0, e1), lo, hi); zb0 = lo + hi;
            }
            if (t >= 1) {
                // tail1(t-1): independent of the dot above (register carry)
                float sa = fast_sigmoid(za1);
                float sb = fast_sigmoid(type ? zb1 : (zb1 + zb1));
                float rb = type ? sb : (2.f * sb - 1.f);
                float send = type ? sa : (sa * rb);
                float recv = __shfl_xor_sync(FULL, send, 1);
                float fg  = type ? sa : recv;
                float inc = type ? recv : send;
                c0_1 = fmaf(fg, c0_1, inc);
                float th = 2.f * fast_sigmoid(c0_1 + c0_1) - 1.f;
                if (type) h1_sh[u] = rb * th;
            }
        } else {
            if (t >= 1) {
                // layer-1 batch0, step t-1: reads h0_sh = h0(t-1)
                float p = 0.f;
                #pragma unroll
                for (int j = 0; j < 8; ++j)
                    p = fmaf(h0_sh[l1bk + 8 * j], w1r[j], p);
                p += __shfl_xor_sync(FULL, p, 4);
                p += __shfl_xor_sync(FULL, p, 8);
                p += __shfl_xor_sync(FULL, p, 16);
                float z1 = fmaf(h1L_0, w1h, p + b1v);
                float zz = (l1g == 2) ? (z1 + 1.0f) : z1;
                float sv = (l1g == 1) ? (zz + zz) : zz;
                float sg = fast_sigmoid(sv);
                float r  = (l1g == 1) ? (2.f * sg - 1.f) : sg;
                float ri = __shfl_sync(FULL, r, 0, 4);
                float rj = __shfl_sync(FULL, r, 1, 4);
                float rf = __shfl_sync(FULL, r, 2, 4);
                float ro = __shfl_sync(FULL, r, 3, 4);
                c1_0 = fmaf(rf, c1_0, ri * rj);
                float th = 2.f * fast_sigmoid(c1_0 + c1_0) - 1.f;
                h1L_0 = ro * th;
                if (lane == 0)
                    out[(2 * bb) * T + (t - 1)] = fmaf(h1L_0, wdv, bdv);
            }
        }
        __syncthreads();   // publishes h1(t-1); h0(t-1) reads are done

        // ================= ODD slot =================
        // dot1(t) ; tail0(t) ; layer1 batch1 step t-1
        if (tid < 128) {
            if (t < T) {
                const ulonglong2* hp = (const ulonglong2*)h1_sh;
                unsigned long long f0 = pack2(fmaf(xt1, wxa, ba), 0.f);
                unsigned long long f1 = pack2(0.f, 0.f);
                unsigned long long g0 = pack2(fmaf(xt1, wxb, bb2), 0.f);
                unsigned long long g1 = pack2(0.f, 0.f);
                #pragma unroll
                for (int i = 0; i < 16; ++i) {
                    ulonglong2 hv = hp[i];
                    f0 = fma2(hv.x, wpa[2 * i],     f0);
                    f1 = fma2(hv.y, wpa[2 * i + 1], f1);
                    g0 = fma2(hv.x, wpb[2 * i],     g0);
                    g1 = fma2(hv.y, wpb[2 * i + 1], g1);
                }
                // tail0(t): consumes za0/zb0 from the even slot (independent
                // of the f/g chains above -> overlaps the burst)
                float sa = fast_sigmoid(za0);
                float sb = fast_sigmoid(type ? zb0 : (zb0 + zb0));
                float rb = type ? sb : (2.f * sb - 1.f);
                float send = type ? sa : (sa * rb);
                float recv = __shfl_xor_sync(FULL, send, 1);
                float fg  = type ? sa : recv;
                float inc = type ? recv : send;
                c0_0 = fmaf(fg, c0_0, inc);
                float th = 2.f * fast_sigmoid(c0_0 + c0_0) - 1.f;
                if (type) h0_sh[u] = rb * th;

                float lo, hi;
                unpack2(add2(f0, f1), lo, hi); za1 = lo + hi;
                unpack2(add2(g0, g1), lo, hi); zb1 = lo + hi;
            }
        } else {
            if (t >= 1) {
                // layer-1 batch1, step t-1: reads h1_sh = h1(t-1)
                float p = 0.f;
                #pragma unroll
                for (int j = 0; j < 8; ++j)
                    p = fmaf(h1_sh[l1bk + 8 * j], w1r[j], p);
                p += __shfl_xor_sync(FULL, p, 4);
                p += __shfl_xor_sync(FULL, p, 8);
                p += __shfl_xor_sync(FULL, p, 16);
                float z1 = fmaf(h1L_1, w1h, p + b1v);
                float zz = (l1g == 2) ? (z1 + 1.0f) : z1;
                float sv = (l1g == 1) ? (zz + zz) : zz;
                float sg = fast_sigmoid(sv);
                float r  = (l1g == 1) ? (2.f * sg - 1.f) : sg;
                float ri = __shfl_sync(FULL, r, 0, 4);
                float rj = __shfl_sync(FULL, r, 1, 4);
                float rf = __shfl_sync(FULL, r, 2, 4);
                float ro = __shfl_sync(FULL, r, 3, 4);
                c1_1 = fmaf(rf, c1_1, ri * rj);
                float th = 2.f * fast_sigmoid(c1_1 + c1_1) - 1.f;
                h1L_1 = ro * th;
                if (lane == 0)
                    out[(2 * bb + 1) * T + (t - 1)] = fmaf(h1L_1, wdv, bdv);
            }
        }
        __syncthreads();   // publishes h0(t); h1(t-1) reads are done
    }
}

extern "C" void kernel_launch(void* const* d_in, const int* in_sizes, int n_in,
                              void* d_out, int out_size) {
    const float* x  = (const float*)d_in[0];
    const float* W0 = (const float*)d_in[1];
    const float* b0 = (const float*)d_in[2];
    const float* W1 = (const float*)d_in[3];
    const float* b1 = (const float*)d_in[4];
    const float* Wd = (const float*)d_in[5];
    const float* bd = (const float*)d_in[6];
    float* out = (float*)d_out;
    lstm_stack_kernel<<<128, 160>>>(x, W0, b0, W1, b1, Wd, bd, out);
}

// round 9
// speedup vs baseline: 1.3988x; 1.3988x over previous
#include <cuda_runtime.h>

#define FULL 0xFFFFFFFFu

__device__ __forceinline__ unsigned long long pack2(float a, float b) {
    unsigned long long r;
    asm("mov.b64 %0, {%1, %2};" : "=l"(r) : "f"(a), "f"(b));
    return r;
}
__device__ __forceinline__ void unpack2(unsigned long long p, float& a, float& b) {
    asm("mov.b64 {%0, %1}, %2;" : "=f"(a), "=f"(b) : "l"(p));
}
__device__ __forceinline__ unsigned long long fma2(unsigned long long a,
                                                   unsigned long long b,
                                                   unsigned long long c) {
    unsigned long long d;
    asm("fma.rn.f32x2 %0, %1, %2, %3;" : "=l"(d) : "l"(a), "l"(b), "l"(c));
    return d;
}
__device__ __forceinline__ unsigned long long add2(unsigned long long a,
                                                   unsigned long long b) {
    unsigned long long d;
    asm("add.rn.f32x2 %0, %1, %2;" : "=l"(d) : "l"(a), "l"(b));
    return d;
}

__device__ __forceinline__ float fast_sigmoid(float x) {
    return __fdividef(1.0f, 1.0f + __expf(-x));
}

// One CTA per TWO batches, 160 threads, grid 128 (one CTA/SM, single wave).
// Round 9 ordering: dot0 -> dot1 -> tail0 -> tail1 -> both STS at the END.
// All h LDS precede all h STS within the phase, so no aliasing barrier blocks
// scheduling; z0 is complete at the burst midpoint, letting ptxas overlap
// tail0's ~120-cycle nonlinear latency chain with batch1's fma burst.
// Threads 0..127: layer-0; thread = (unit u, type); type0 owns (i,j),
// type1 owns (f,o); weights register-resident f32x2, shared by both batches.
// Threads 128..159 (warp 4): layer-1 (units=1) + dense for both batches
// (lane halves), one step lagged. One __syncthreads per step.
__global__ __launch_bounds__(160, 1)
void lstm_stack_kernel(const float* __restrict__ x,
                       const float* __restrict__ W0,
                       const float* __restrict__ b0,
                       const float* __restrict__ W1,
                       const float* __restrict__ b1,
                       const float* __restrict__ Wd,
                       const float* __restrict__ bd,
                       float* __restrict__ out)
{
    constexpr int T = 2048;

    const int bb   = blockIdx.x;      // batch pair
    const int tid  = threadIdx.x;
    const int lane = tid & 31;
    const int wid  = tid >> 5;

    __shared__ __align__(16) float x_sh[2][T];
    __shared__ __align__(16) float h_sh[2][2][64];   // [buffer][batch][unit]
    __shared__ float red[5];
    __shared__ float inv_sh[2];

    // ---- Phase 0: load both x tiles, l2-normalize over time ----
    for (int bi = 0; bi < 2; ++bi) {
        const float* xb = x + (2 * bb + bi) * T;
        float ps = 0.f;
        for (int i = tid; i < T; i += 160) {
            float v = xb[i];
            x_sh[bi][i] = v;
            ps = fmaf(v, v, ps);
        }
        #pragma unroll
        for (int o = 16; o > 0; o >>= 1) ps += __shfl_xor_sync(FULL, ps, o);
        if (lane == 0) red[wid] = ps;
        __syncthreads();
        if (tid == 0) {
            float s = 0.f;
            #pragma unroll
            for (int i = 0; i < 5; ++i) s += red[i];
            inv_sh[bi] = rsqrtf(fmaxf(s, 1e-12f));
        }
        __syncthreads();               // also protects red[] reuse
    }
    {
        float i0 = inv_sh[0], i1 = inv_sh[1];
        for (int i = tid; i < T; i += 160) {
            x_sh[0][i] *= i0;
            x_sh[1][i] *= i1;
        }
    }
    if (tid < 128) ((float*)h_sh[0])[tid] = 0.f;   // h_{-1} = 0, both batches
    // (ordered by the sync at the top of the main loop)

    // ---- Per-thread persistent state / weights ----
    const int u    = tid >> 1;
    const int type = tid & 1;           // 0: (i,j)   1: (f,o)
    unsigned long long wpa[32], wpb[32];
    float wxa = 0.f, wxb = 0.f, ba = 0.f, bb2 = 0.f;
    float c0_0 = 0.f, c0_1 = 0.f;

    // layer-1 (warp 4) state: lanes 0-15 -> batch0, 16-31 -> batch1
    const int l1b  = lane >> 4;
    const int l1g  = lane & 3;
    const int l1bk = (lane >> 2) & 3;
    float w1r[16];
    float w1h = 0.f, b1v = 0.f, wdv = 0.f, bdv = 0.f;
    float c1 = 0.f, h1 = 0.f;

    if (tid < 128) {
        const int ca = u + (type ? 128 : 0);   // i or f column
        const int cb = ca + 64;                // j or o column
        wxa = W0[ca];
        wxb = W0[cb];
        ba  = b0[ca] + (type ? 1.0f : 0.0f);   // fold FORGET_BIAS
        bb2 = b0[cb];
        #pragma unroll
        for (int p = 0; p < 32; ++p) {
            wpa[p] = pack2(W0[(1 + 2 * p) * 256 + ca], W0[(2 + 2 * p) * 256 + ca]);
            wpb[p] = pack2(W0[(1 + 2 * p) * 256 + cb], W0[(2 + 2 * p) * 256 + cb]);
        }
    } else {
        #pragma unroll
        for (int j = 0; j < 16; ++j)
            w1r[j] = W1[(l1bk + 4 * j) * 4 + l1g];
        w1h = W1[64 * 4 + l1g];
        b1v = b1[l1g];
        wdv = Wd[0];
        bdv = bd[0];
    }

    // ---- Main recurrence: t = 0..T. Layer-0 active for t<T, layer-1
    // processes step t-1 (final iteration drains layer-1). ----
    #pragma unroll 1
    for (int t = 0; t <= T; ++t) {
        // prefetch x (read-only, no barrier dependency)
        const int tt = (t < T) ? t : 0;
        float xt0 = x_sh[0][tt];
        float xt1 = x_sh[1][tt];
        __syncthreads();                 // h_sh[t&1] = h_{t-1} now valid
        const int cur = t & 1;
        if (tid < 128) {
            if (t < T) {
                const ulonglong2* hp0 = (const ulonglong2*)h_sh[cur][0];
                const ulonglong2* hp1 = (const ulonglong2*)h_sh[cur][1];
                unsigned long long zero = pack2(0.f, 0.f);

                // ======== dot 0 (batch 0) ========
                unsigned long long a0 = pack2(fmaf(xt0, wxa, ba), 0.f);
                unsigned long long a1 = zero;
                unsigned long long e0 = pack2(fmaf(xt0, wxb, bb2), 0.f);
                unsigned long long e1 = zero;
                #pragma unroll
                for (int i = 0; i < 16; ++i) {
                    ulonglong2 hv = hp0[i];
                    a0 = fma2(hv.x, wpa[2 * i],     a0);
                    a1 = fma2(hv.y, wpa[2 * i + 1], a1);
                    e0 = fma2(hv.x, wpb[2 * i],     e0);
                    e1 = fma2(hv.y, wpb[2 * i + 1], e1);
                }
                float za0, zb0;
                {
                    float lo, hi;
                    unpack2(add2(a0, a1), lo, hi); za0 = lo + hi;
                    unpack2(add2(e0, e1), lo, hi); zb0 = lo + hi;
                }

                // ======== dot 1 (batch 1) ========
                unsigned long long f0 = pack2(fmaf(xt1, wxa, ba), 0.f);
                unsigned long long f1 = zero;
                unsigned long long g0 = pack2(fmaf(xt1, wxb, bb2), 0.f);
                unsigned long long g1 = zero;
                #pragma unroll
                for (int i = 0; i < 16; ++i) {
                    ulonglong2 hv = hp1[i];
                    f0 = fma2(hv.x, wpa[2 * i],     f0);
                    f1 = fma2(hv.y, wpa[2 * i + 1], f1);
                    g0 = fma2(hv.x, wpb[2 * i],     g0);
                    g1 = fma2(hv.y, wpb[2 * i + 1], g1);
                }
                float za1, zb1;
                {
                    float lo, hi;
                    unpack2(add2(f0, f1), lo, hi); za1 = lo + hi;
                    unpack2(add2(g0, g1), lo, hi); zb1 = lo + hi;
                }

                // ======== tail 0 (z0 ready since burst midpoint) ========
                float sa0 = fast_sigmoid(za0);
                float sb0 = fast_sigmoid(type ? zb0 : (zb0 + zb0));
                float rb0 = type ? sb0 : (2.f * sb0 - 1.f);
                float send0 = type ? sa0 : (sa0 * rb0);
                float recv0 = __shfl_xor_sync(FULL, send0, 1);
                float fg0  = type ? sa0 : recv0;
                float inc0 = type ? recv0 : send0;
                c0_0 = fmaf(fg0, c0_0, inc0);
                float th0 = 2.f * fast_sigmoid(c0_0 + c0_0) - 1.f;
                float h0 = rb0 * th0;     // valid on type1 (rb = sigma(o))

                // ======== tail 1 ========
                float sa1 = fast_sigmoid(za1);
                float sb1 = fast_sigmoid(type ? zb1 : (zb1 + zb1));
                float rb1 = type ? sb1 : (2.f * sb1 - 1.f);
                float send1 = type ? sa1 : (sa1 * rb1);
                float recv1 = __shfl_xor_sync(FULL, send1, 1);
                float fg1  = type ? sa1 : recv1;
                float inc1 = type ? recv1 : send1;
                c0_1 = fmaf(fg1, c0_1, inc1);
                float th1 = 2.f * fast_sigmoid(c0_1 + c0_1) - 1.f;
                float h1v = rb1 * th1;

                // ======== publish (all STS after all LDS) ========
                if (type) {
                    h_sh[cur ^ 1][0][u] = h0;
                    h_sh[cur ^ 1][1][u] = h1v;
                }
            }
        } else {
            if (t >= 1) {
                // layer-1 for step s = t-1, input h_sh[cur][l1b]
                const float* hv = h_sh[cur][l1b];
                float p = 0.f;
                #pragma unroll
                for (int j = 0; j < 16; ++j)
                    p = fmaf(hv[l1bk + 4 * j], w1r[j], p);
                p += __shfl_xor_sync(FULL, p, 4);    // stays within 16-lane half
                p += __shfl_xor_sync(FULL, p, 8);
                float z1 = fmaf(h1, w1h, p + b1v);

                float zz = (l1g == 2) ? (z1 + 1.0f) : z1;
                float sv = (l1g == 1) ? (zz + zz) : zz;
                float sg = fast_sigmoid(sv);
                float r  = (l1g == 1) ? (2.f * sg - 1.f) : sg;

                float ri = __shfl_sync(FULL, r, 0, 4);
                float rj = __shfl_sync(FULL, r, 1, 4);
                float rf = __shfl_sync(FULL, r, 2, 4);
                float ro = __shfl_sync(FULL, r, 3, 4);
                c1 = fmaf(rf, c1, ri * rj);
                float th = 2.f * fast_sigmoid(c1 + c1) - 1.f;
                h1 = ro * th;
                if ((lane & 15) == 0)
                    out[(2 * bb + l1b) * T + (t - 1)] = fmaf(h1, wdv, bdv);
            }
        }
    }
}

extern "C" void kernel_launch(void* const* d_in, const int* in_sizes, int n_in,
                              void* d_out, int out_size) {
    const float* x  = (const float*)d_in[0];
    const float* W0 = (const float*)d_in[1];
    const float* b0 = (const float*)d_in[2];
    const float* W1 = (const float*)d_in[3];
    const float* b1 = (const float*)d_in[4];
    const float* Wd = (const float*)d_in[5];
    const float* bd = (const float*)d_in[6];
    float* out = (float*)d_out;
    lstm_stack_kernel<<<128, 160>>>(x, W0, b0, W1, b1, Wd, bd, out);
}